// round 2
// baseline (speedup 1.0000x reference)
#include <cuda_runtime.h>
#include <cstdint>

#define BSZ   2048
#define HID   2048
#define PIN   9408
#define POUT  1024
#define NC    65
#define KFC   3072   /* HID + POUT */

// ---------------- scratch (no allocations allowed) ----------------
__device__ float g_colsum[POUT];
__device__ float g_s2[NC];          // S2[c] + BSZ*b_fc[c]
__device__ float g_s1[BSZ * NC];

// ---------------- helpers ----------------
__device__ __forceinline__ unsigned f2tf32(float f) {
    unsigned r;
    asm("cvt.rna.tf32.f32 %0, %1;" : "=r"(r) : "f"(f));
    return r;
}

// ---------------- kernel 0: zero scratch ----------------
__global__ void zero_kernel() {
    int i = blockIdx.x * blockDim.x + threadIdx.x;
    if (i < POUT) g_colsum[i] = 0.f;
    if (i < BSZ * NC) g_s1[i] = 0.f;
}

// ---------------- kernel 1: big GEMM  colsum[n] = sum_m relu(z2f @ Wp^T + b)[m,n] ----------------
#define BM 128
#define BN 128
#define BK 16
#define SST 20                       /* smem row stride (uints), conflict-free frag loads */
#define KTILES (PIN / BK)            /* 588 */

__global__ __launch_bounds__(256) void gemm_colsum(const float* __restrict__ A,   // z2 [BSZ][PIN]
                                                   const float* __restrict__ B,   // W_proj [POUT][PIN]
                                                   const float* __restrict__ bias) // b_proj [POUT]
{
    __shared__ unsigned As[2][BM * SST];
    __shared__ unsigned Bs[2][BN * SST];
    __shared__ float colsum_sh[BN];

    const int tid  = threadIdx.x;
    const int lane = tid & 31;
    const int wid  = tid >> 5;
    const int g    = lane >> 2;      // group id (0..7)
    const int t    = lane & 3;       // thread in group
    const int warp_m = wid >> 1;     // 0..3 (32 rows each)
    const int warp_n = wid & 1;      // 0..1 (64 cols each)
    const int m0 = blockIdx.x * BM;
    const int n0 = blockIdx.y * BN;

    const int r = tid >> 2;          // staging row (0..63), also r+64
    const int q = tid & 3;           // staging quad (float4 index within BK row)

    if (tid < BN) colsum_sh[tid] = 0.f;

    float acc[2][8][4];
#pragma unroll
    for (int a = 0; a < 2; ++a)
#pragma unroll
        for (int b = 0; b < 8; ++b)
#pragma unroll
            for (int c = 0; c < 4; ++c) acc[a][b][c] = 0.f;

    const float* Ap0 = A + (long)(m0 + r)      * PIN + q * 4;
    const float* Ap1 = A + (long)(m0 + r + 64) * PIN + q * 4;
    const float* Bp0 = B + (long)(n0 + r)      * PIN + q * 4;
    const float* Bp1 = B + (long)(n0 + r + 64) * PIN + q * 4;
    const int s0 = r * SST + q * 4;
    const int s1i = (r + 64) * SST + q * 4;

    float4 fa0 = *(const float4*)Ap0;
    float4 fa1 = *(const float4*)Ap1;
    float4 fb0 = *(const float4*)Bp0;
    float4 fb1 = *(const float4*)Bp1;

    auto stash = [&](int buf, float4 va0, float4 va1, float4 vb0, float4 vb1) {
        uint4 u;
        u.x = f2tf32(va0.x); u.y = f2tf32(va0.y); u.z = f2tf32(va0.z); u.w = f2tf32(va0.w);
        *(uint4*)&As[buf][s0]  = u;
        u.x = f2tf32(va1.x); u.y = f2tf32(va1.y); u.z = f2tf32(va1.z); u.w = f2tf32(va1.w);
        *(uint4*)&As[buf][s1i] = u;
        u.x = f2tf32(vb0.x); u.y = f2tf32(vb0.y); u.z = f2tf32(vb0.z); u.w = f2tf32(vb0.w);
        *(uint4*)&Bs[buf][s0]  = u;
        u.x = f2tf32(vb1.x); u.y = f2tf32(vb1.y); u.z = f2tf32(vb1.z); u.w = f2tf32(vb1.w);
        *(uint4*)&Bs[buf][s1i] = u;
    };

    stash(0, fa0, fa1, fb0, fb1);
    __syncthreads();

    int p = 0;
#pragma unroll 1
    for (int kt = 0; kt < KTILES; ++kt) {
        if (kt + 1 < KTILES) {
            const int off = (kt + 1) * BK;
            fa0 = *(const float4*)(Ap0 + off);
            fa1 = *(const float4*)(Ap1 + off);
            fb0 = *(const float4*)(Bp0 + off);
            fb1 = *(const float4*)(Bp1 + off);
        }

#pragma unroll
        for (int ks = 0; ks < BK; ks += 8) {
            unsigned af[2][4];
#pragma unroll
            for (int mt = 0; mt < 2; ++mt) {
                const int rb = (warp_m * 32 + mt * 16 + g) * SST + ks + t;
                af[mt][0] = As[p][rb];
                af[mt][1] = As[p][rb + 8 * SST];
                af[mt][2] = As[p][rb + 4];
                af[mt][3] = As[p][rb + 8 * SST + 4];
            }
#pragma unroll
            for (int nt = 0; nt < 8; ++nt) {
                const int nb = (warp_n * 64 + nt * 8 + g) * SST + ks + t;
                const unsigned b0 = Bs[p][nb];
                const unsigned b1 = Bs[p][nb + 4];
#pragma unroll
                for (int mt = 0; mt < 2; ++mt) {
                    asm volatile(
                        "mma.sync.aligned.m16n8k8.row.col.f32.tf32.tf32.f32 "
                        "{%0,%1,%2,%3}, {%4,%5,%6,%7}, {%8,%9}, {%0,%1,%2,%3};"
                        : "+f"(acc[mt][nt][0]), "+f"(acc[mt][nt][1]),
                          "+f"(acc[mt][nt][2]), "+f"(acc[mt][nt][3])
                        : "r"(af[mt][0]), "r"(af[mt][1]), "r"(af[mt][2]), "r"(af[mt][3]),
                          "r"(b0), "r"(b1));
                }
            }
        }

        if (kt + 1 < KTILES) stash(p ^ 1, fa0, fa1, fb0, fb1);
        __syncthreads();
        p ^= 1;
    }

    // Epilogue: relu(acc + bias), reduce over all M rows into per-column sums.
#pragma unroll
    for (int nt = 0; nt < 8; ++nt) {
#pragma unroll
        for (int pc = 0; pc < 2; ++pc) {
            const int col = warp_n * 64 + nt * 8 + 2 * t + pc;
            const float bv = bias[n0 + col];
            float v = fmaxf(acc[0][nt][pc]     + bv, 0.f)
                    + fmaxf(acc[0][nt][2 + pc] + bv, 0.f)
                    + fmaxf(acc[1][nt][pc]     + bv, 0.f)
                    + fmaxf(acc[1][nt][2 + pc] + bv, 0.f);
            v += __shfl_xor_sync(0xffffffffu, v, 4);
            v += __shfl_xor_sync(0xffffffffu, v, 8);
            v += __shfl_xor_sync(0xffffffffu, v, 16);
            if (g == 0) atomicAdd(&colsum_sh[col], v);
        }
    }
    __syncthreads();
    if (tid < BN) atomicAdd(&g_colsum[n0 + tid], colsum_sh[tid]);
}

// ---------------- kernel 2: S2[c] = colsum . W_fc[c, HID:] + BSZ*b_fc[c] ----------------
__global__ void s2_kernel(const float* __restrict__ Wfc, const float* __restrict__ bfc) {
    const int c = blockIdx.x;
    const int tid = threadIdx.x;
    float pacc = 0.f;
    for (int k = tid; k < POUT; k += 256)
        pacc += g_colsum[k] * Wfc[(long)c * KFC + HID + k];
#pragma unroll
    for (int off = 16; off > 0; off >>= 1)
        pacc += __shfl_down_sync(0xffffffffu, pacc, off);
    __shared__ float red[8];
    if ((tid & 31) == 0) red[tid >> 5] = pacc;
    __syncthreads();
    if (tid == 0) {
        float s = 0.f;
#pragma unroll
        for (int i = 0; i < 8; ++i) s += red[i];
        g_s2[c] = s + (float)BSZ * bfc[c];
    }
}

// ---------------- kernel 3: s1 = z1 @ W_fc[:, :HID]^T  (fp32, K-split + atomics) ----------------
#define S1_BM 128
#define S1_KS 8
#define S1_CHUNK (HID / S1_KS)   /* 256 */
#define S1_KC 32

__global__ __launch_bounds__(256) void s1_kernel(const float* __restrict__ z1,
                                                 const float* __restrict__ Wfc) {
    __shared__ float zt[S1_KC][S1_BM + 4];   // [k][row], transposed
    __shared__ float ws[S1_KC][80];          // [k][col], cols padded to 80

    const int tid = threadIdx.x;
    const int tx = tid & 15;                 // col tile: cols tx*5 .. tx*5+4
    const int ty = tid >> 4;                 // row tile: rows ty*8 .. ty*8+7
    const int rb = blockIdx.x * S1_BM;
    const int kbase = blockIdx.y * S1_CHUNK;

    float acc[8][5];
#pragma unroll
    for (int i = 0; i < 8; ++i)
#pragma unroll
        for (int j = 0; j < 5; ++j) acc[i][j] = 0.f;

    for (int kc = kbase; kc < kbase + S1_CHUNK; kc += S1_KC) {
#pragma unroll
        for (int i = 0; i < 16; ++i) {
            const int idx = tid + i * 256;       // 4096 elems
            const int k = idx & 31, rr = idx >> 5;
            zt[k][rr] = z1[(long)(rb + rr) * HID + kc + k];
        }
#pragma unroll
        for (int i = 0; i < 10; ++i) {
            const int idx = tid + i * 256;       // 2560 slots
            const int c = idx % 80, k = idx / 80;
            ws[k][c] = (c < NC) ? Wfc[(long)c * KFC + kc + k] : 0.f;
        }
        __syncthreads();

#pragma unroll
        for (int k = 0; k < S1_KC; ++k) {
            const float4 za = *(const float4*)&zt[k][ty * 8];
            const float4 zb = *(const float4*)&zt[k][ty * 8 + 4];
            float w[5];
#pragma unroll
            for (int j = 0; j < 5; ++j) w[j] = ws[k][tx * 5 + j];
            const float zr[8] = {za.x, za.y, za.z, za.w, zb.x, zb.y, zb.z, zb.w};
#pragma unroll
            for (int i = 0; i < 8; ++i)
#pragma unroll
                for (int j = 0; j < 5; ++j) acc[i][j] += zr[i] * w[j];
        }
        __syncthreads();
    }

#pragma unroll
    for (int i = 0; i < 8; ++i) {
        const int row = rb + ty * 8 + i;
#pragma unroll
        for (int j = 0; j < 5; ++j) {
            const int c = tx * 5 + j;
            if (c < NC) atomicAdd(&g_s1[(long)row * NC + c], acc[i][j]);
        }
    }
}

// ---------------- kernel 4: out[i,c] = 2048*s1[i,c] + (S2[c] + 2048*b_fc[c]) ----------------
__global__ void final_kernel(float* __restrict__ out) {
    const int i = blockIdx.x * blockDim.x + threadIdx.x;
    if (i < BSZ * NC) out[i] = 2048.f * g_s1[i] + g_s2[i % NC];
}

// ---------------- launch ----------------
extern "C" void kernel_launch(void* const* d_in, const int* in_sizes, int n_in,
                              void* d_out, int out_size) {
    (void)in_sizes; (void)n_in; (void)out_size;
    const float* z1  = (const float*)d_in[0];
    const float* z2  = (const float*)d_in[1];
    const float* Wp  = (const float*)d_in[2];
    const float* bp  = (const float*)d_in[3];
    const float* Wfc = (const float*)d_in[4];
    const float* bfc = (const float*)d_in[5];
    float* out = (float*)d_out;

    zero_kernel<<<(BSZ * NC + 255) / 256, 256>>>();
    gemm_colsum<<<dim3(BSZ / BM, POUT / BN), 256>>>(z2, Wp, bp);
    s1_kernel<<<dim3(BSZ / S1_BM, S1_KS), 256>>>(z1, Wfc);
    s2_kernel<<<NC, 256>>>(Wfc, bfc);
    final_kernel<<<(BSZ * NC + 255) / 256, 256>>>(out);
}

// round 5
// speedup vs baseline: 2.0237x; 2.0237x over previous
#include <cuda_runtime.h>
#include <cuda_fp16.h>
#include <cstdint>

#define BSZ   2048
#define HID   2048
#define PIN   9408
#define POUT  1024
#define NC    65
#define KFC   3072   /* HID + POUT */

// ---------------- scratch (no allocations allowed) ----------------
__device__ float g_colsum[POUT];
__device__ float g_s2[NC];
__device__ float g_s1[BSZ * NC];
__device__ __align__(16) __half g_Ah[BSZ * PIN];   // z2 in fp16
__device__ __align__(16) __half g_Bh[POUT * PIN];  // W_proj in fp16

// ---------------- helpers ----------------
__device__ __forceinline__ uint32_t smem_u32(const void* p) {
    uint32_t a;
    asm("{ .reg .u64 t; cvta.to.shared.u64 t, %1; cvt.u32.u64 %0, t; }" : "=r"(a) : "l"(p));
    return a;
}
#define CP_ASYNC16(sa, ga) \
    asm volatile("cp.async.cg.shared.global [%0], [%1], 16;" :: "r"((uint32_t)(sa)), "l"(ga) : "memory")
#define CP_COMMIT() asm volatile("cp.async.commit_group;" ::: "memory")
#define CP_WAIT1()  asm volatile("cp.async.wait_group 1;" ::: "memory")

// ---------------- kernel 0: zero scratch ----------------
__global__ void zero_kernel() {
    int i = blockIdx.x * blockDim.x + threadIdx.x;
    if (i < POUT) g_colsum[i] = 0.f;
    if (i < BSZ * NC) g_s1[i] = 0.f;
}

// ---------------- fp32 -> fp16 conversion (8 elems / thread) ----------------
__global__ void cvt8_kernel(const float* __restrict__ s, int which, int n8) {
    int i = blockIdx.x * blockDim.x + threadIdx.x;
    if (i >= n8) return;
    __half* d = which ? g_Bh : g_Ah;
    const float4* s4 = (const float4*)s;
    float4 a = s4[2 * i], b = s4[2 * i + 1];
    union { uint4 u; __half h[8]; } o;
    o.h[0] = __float2half_rn(a.x); o.h[1] = __float2half_rn(a.y);
    o.h[2] = __float2half_rn(a.z); o.h[3] = __float2half_rn(a.w);
    o.h[4] = __float2half_rn(b.x); o.h[5] = __float2half_rn(b.y);
    o.h[6] = __float2half_rn(b.z); o.h[7] = __float2half_rn(b.w);
    ((uint4*)d)[i] = o.u;
}

// ---------------- kernel 1: fp16 mma.sync GEMM + relu + colsum ----------------
// colsum[n] = sum_m relu( (z2f @ W_proj^T)[m,n] + b_proj[n] )
#define BM 128
#define BN 128
#define BK 32                       /* k elems per chunk */
#define NST 3                       /* pipeline stages */
#define SST 20                      /* uint32 words per smem row (16 data + 4 pad) */
#define TILE_W (BM * SST)           /* 2560 words = 10240 B per tile */
#define NK (PIN / BK)               /* 294 chunks */

__global__ __launch_bounds__(256) void gemm_fd(const float* __restrict__ bias) {
    extern __shared__ uint32_t sh[];
    uint32_t* As = sh;                     // [NST][TILE_W]
    uint32_t* Bs = sh + NST * TILE_W;      // [NST][TILE_W]
    __shared__ float colsum_sh[BN];
    __shared__ float bias_sh[BN];

    const int tid  = threadIdx.x;
    const int lane = tid & 31;
    const int wid  = tid >> 5;
    const int g    = lane >> 2;      // 0..7
    const int t    = lane & 3;       // 0..3
    const int warp_m = wid >> 1;     // 0..3 -> 32 rows each
    const int warp_n = wid & 1;      // 0..1 -> 64 cols each
    const int m0 = blockIdx.x * BM;
    const int n0 = blockIdx.y * BN;

    if (tid < BN) { colsum_sh[tid] = 0.f; bias_sh[tid] = bias[n0 + tid]; }

    float acc[2][8][4];
#pragma unroll
    for (int a = 0; a < 2; ++a)
#pragma unroll
        for (int b = 0; b < 8; ++b)
#pragma unroll
            for (int c = 0; c < 4; ++c) acc[a][b][c] = 0.f;

    // --- loader setup: 512 x 16B chunks per tile, 2 per thread ---
    const uint32_t sA = smem_u32(As);
    const uint32_t sB = smem_u32(Bs);
    int rowL[2], qL[2];
    const __half* gA[2];
    const __half* gB[2];
#pragma unroll
    for (int i = 0; i < 2; ++i) {
        const int c = tid + i * 256;
        rowL[i] = c >> 2;                 // 0..127
        qL[i]   = c & 3;                  // word-quad within 16-word row
        gA[i] = g_Ah + (size_t)(m0 + rowL[i]) * PIN + qL[i] * 8;
        gB[i] = g_Bh + (size_t)(n0 + rowL[i]) * PIN + qL[i] * 8;
    }

    auto load_stage = [&](int s, int kt) {
        const int kc = kt * BK;
#pragma unroll
        for (int i = 0; i < 2; ++i) {
            const uint32_t off = (uint32_t)(s * TILE_W * 4 + rowL[i] * (SST * 4) + qL[i] * 16);
            CP_ASYNC16(sA + off, gA[i] + kc);
            CP_ASYNC16(sB + off, gB[i] + kc);
        }
    };

    // prologue: stages 0,1
    load_stage(0, 0); CP_COMMIT();
    load_stage(1, 1); CP_COMMIT();
    __syncthreads();

#pragma unroll 1
    for (int kt = 0; kt < NK; ++kt) {
        CP_WAIT1();                 // chunk kt resident
        __syncthreads();            // also: all warps done computing chunk kt-1 (stage reuse safe)

        if (kt + 2 < NK) load_stage((kt + 2) % NST, kt + 2);
        CP_COMMIT();

        const uint32_t* Ab = As + (kt % NST) * TILE_W;
        const uint32_t* Bb = Bs + (kt % NST) * TILE_W;

#pragma unroll
        for (int ks2 = 0; ks2 < 16; ks2 += 8) {      // two k=16 halves of BK=32
            unsigned af[2][4];
#pragma unroll
            for (int mt = 0; mt < 2; ++mt) {
                const int rb = (warp_m * 32 + mt * 16 + g) * SST + ks2 + t;
                af[mt][0] = Ab[rb];
                af[mt][1] = Ab[rb + 8 * SST];
                af[mt][2] = Ab[rb + 4];
                af[mt][3] = Ab[rb + 8 * SST + 4];
            }
#pragma unroll
            for (int nt = 0; nt < 8; ++nt) {
                const int nb = (warp_n * 64 + nt * 8 + g) * SST + ks2 + t;
                const unsigned b0 = Bb[nb];
                const unsigned b1 = Bb[nb + 4];
#pragma unroll
                for (int mt = 0; mt < 2; ++mt) {
                    asm volatile(
                        "mma.sync.aligned.m16n8k16.row.col.f32.f16.f16.f32 "
                        "{%0,%1,%2,%3}, {%4,%5,%6,%7}, {%8,%9}, {%0,%1,%2,%3};"
                        : "+f"(acc[mt][nt][0]), "+f"(acc[mt][nt][1]),
                          "+f"(acc[mt][nt][2]), "+f"(acc[mt][nt][3])
                        : "r"(af[mt][0]), "r"(af[mt][1]), "r"(af[mt][2]), "r"(af[mt][3]),
                          "r"(b0), "r"(b1));
                }
            }
        }
        __syncthreads();
    }

    // ---- epilogue: relu(acc + bias), reduce all M rows -> per-column sums ----
#pragma unroll
    for (int nt = 0; nt < 8; ++nt) {
#pragma unroll
        for (int pc = 0; pc < 2; ++pc) {
            const int col = warp_n * 64 + nt * 8 + 2 * t + pc;
            const float bv = bias_sh[col];
            float v = fmaxf(acc[0][nt][pc]     + bv, 0.f)
                    + fmaxf(acc[0][nt][2 + pc] + bv, 0.f)
                    + fmaxf(acc[1][nt][pc]     + bv, 0.f)
                    + fmaxf(acc[1][nt][2 + pc] + bv, 0.f);
            v += __shfl_xor_sync(0xffffffffu, v, 4);
            v += __shfl_xor_sync(0xffffffffu, v, 8);
            v += __shfl_xor_sync(0xffffffffu, v, 16);
            if (g == 0) atomicAdd(&colsum_sh[col], v);
        }
    }
    __syncthreads();
    if (tid < BN) atomicAdd(&g_colsum[n0 + tid], colsum_sh[tid]);
}

#define GEMM_SMEM (NST * TILE_W * 2 * 4)   /* 61440 bytes */

// ---------------- kernel 2: S2[c] = colsum . W_fc[c, HID:] + BSZ*b_fc[c] ----------------
__global__ void s2_kernel(const float* __restrict__ Wfc, const float* __restrict__ bfc) {
    const int c = blockIdx.x;
    const int tid = threadIdx.x;
    float pacc = 0.f;
    for (int k = tid; k < POUT; k += 256)
        pacc += g_colsum[k] * Wfc[(long)c * KFC + HID + k];
#pragma unroll
    for (int off = 16; off > 0; off >>= 1)
        pacc += __shfl_down_sync(0xffffffffu, pacc, off);
    __shared__ float red[8];
    if ((tid & 31) == 0) red[tid >> 5] = pacc;
    __syncthreads();
    if (tid == 0) {
        float s = 0.f;
#pragma unroll
        for (int i = 0; i < 8; ++i) s += red[i];
        g_s2[c] = s + (float)BSZ * bfc[c];
    }
}

// ---------------- kernel 3: s1 = z1 @ W_fc[:, :HID]^T  (fp32) ----------------
#define S1_BM 128
#define S1_KS 8
#define S1_CHUNK (HID / S1_KS)
#define S1_KC 32

__global__ __launch_bounds__(256) void s1_kernel(const float* __restrict__ z1,
                                                 const float* __restrict__ Wfc) {
    __shared__ float zt[S1_KC][S1_BM + 4];
    __shared__ float ws[S1_KC][80];

    const int tid = threadIdx.x;
    const int tx = tid & 15;
    const int ty = tid >> 4;
    const int rb = blockIdx.x * S1_BM;
    const int kbase = blockIdx.y * S1_CHUNK;

    float acc[8][5];
#pragma unroll
    for (int i = 0; i < 8; ++i)
#pragma unroll
        for (int j = 0; j < 5; ++j) acc[i][j] = 0.f;

    for (int kc = kbase; kc < kbase + S1_CHUNK; kc += S1_KC) {
#pragma unroll
        for (int i = 0; i < 16; ++i) {
            const int idx = tid + i * 256;
            const int k = idx & 31, rr = idx >> 5;
            zt[k][rr] = z1[(long)(rb + rr) * HID + kc + k];
        }
#pragma unroll
        for (int i = 0; i < 10; ++i) {
            const int idx = tid + i * 256;
            const int c = idx % 80, k = idx / 80;
            ws[k][c] = (c < NC) ? Wfc[(long)c * KFC + kc + k] : 0.f;
        }
        __syncthreads();

#pragma unroll
        for (int k = 0; k < S1_KC; ++k) {
            const float4 za = *(const float4*)&zt[k][ty * 8];
            const float4 zb = *(const float4*)&zt[k][ty * 8 + 4];
            float w[5];
#pragma unroll
            for (int j = 0; j < 5; ++j) w[j] = ws[k][tx * 5 + j];
            const float zr[8] = {za.x, za.y, za.z, za.w, zb.x, zb.y, zb.z, zb.w};
#pragma unroll
            for (int i = 0; i < 8; ++i)
#pragma unroll
                for (int j = 0; j < 5; ++j) acc[i][j] += zr[i] * w[j];
        }
        __syncthreads();
    }

#pragma unroll
    for (int i = 0; i < 8; ++i) {
        const int row = rb + ty * 8 + i;
#pragma unroll
        for (int j = 0; j < 5; ++j) {
            const int c = tx * 5 + j;
            if (c < NC) atomicAdd(&g_s1[(long)row * NC + c], acc[i][j]);
        }
    }
}

// ---------------- kernel 4: out[i,c] = 2048*s1[i,c] + g_s2[c] ----------------
__global__ void final_kernel(float* __restrict__ out) {
    const int i = blockIdx.x * blockDim.x + threadIdx.x;
    if (i < BSZ * NC) out[i] = 2048.f * g_s1[i] + g_s2[i % NC];
}

// ---------------- launch ----------------
extern "C" void kernel_launch(void* const* d_in, const int* in_sizes, int n_in,
                              void* d_out, int out_size) {
    (void)in_sizes; (void)n_in; (void)out_size;
    const float* z1  = (const float*)d_in[0];
    const float* z2  = (const float*)d_in[1];
    const float* Wp  = (const float*)d_in[2];
    const float* bp  = (const float*)d_in[3];
    const float* Wfc = (const float*)d_in[4];
    const float* bfc = (const float*)d_in[5];
    float* out = (float*)d_out;

    cudaFuncSetAttribute(gemm_fd, cudaFuncAttributeMaxDynamicSharedMemorySize, GEMM_SMEM);

    zero_kernel<<<(BSZ * NC + 255) / 256, 256>>>();
    cvt8_kernel<<<(BSZ * PIN / 8 + 255) / 256, 256>>>(z2, 0, BSZ * PIN / 8);
    cvt8_kernel<<<(POUT * PIN / 8 + 255) / 256, 256>>>(Wp, 1, POUT * PIN / 8);
    gemm_fd<<<dim3(BSZ / BM, POUT / BN), 256, GEMM_SMEM>>>(bp);
    s1_kernel<<<dim3(BSZ / S1_BM, S1_KS), 256>>>(z1, Wfc);
    s2_kernel<<<NC, 256>>>(Wfc, bfc);
    final_kernel<<<(BSZ * NC + 255) / 256, 256>>>(out);
}

// round 9
// speedup vs baseline: 2.2435x; 1.1086x over previous
#include <cuda_runtime.h>
#include <cuda_fp16.h>
#include <cstdint>

#define BSZ   2048
#define HID   2048
#define PIN   9408
#define POUT  1024
#define NC    65
#define KFC   3072   /* HID + POUT */

// ---------------- scratch (no allocations allowed) ----------------
__device__ float g_colsum[POUT];
__device__ float g_s2[NC];
__device__ float g_s1[BSZ * NC];
__device__ __align__(16) __half g_Ah[BSZ * PIN];   // z2 in fp16
__device__ __align__(16) __half g_Bh[POUT * PIN];  // W_proj in fp16

// ---------------- helpers ----------------
__device__ __forceinline__ uint32_t smem_u32(const void* p) {
    uint32_t a;
    asm("{ .reg .u64 t; cvta.to.shared.u64 t, %1; cvt.u32.u64 %0, t; }" : "=r"(a) : "l"(p));
    return a;
}
#define CP_ASYNC16(sa, ga) \
    asm volatile("cp.async.cg.shared.global [%0], [%1], 16;" :: "r"((uint32_t)(sa)), "l"(ga) : "memory")
#define CP_COMMIT() asm volatile("cp.async.commit_group;" ::: "memory")
#define CP_WAIT1()  asm volatile("cp.async.wait_group 1;" ::: "memory")

// ---------------- kernel 0: zero scratch ----------------
__global__ void zero_kernel() {
    int i = blockIdx.x * blockDim.x + threadIdx.x;
    if (i < POUT) g_colsum[i] = 0.f;
    if (i < BSZ * NC) g_s1[i] = 0.f;
}

// ---------------- fp32 -> fp16 conversion (8 elems / thread) ----------------
__global__ void cvt8_kernel(const float* __restrict__ s, int which, int n8) {
    int i = blockIdx.x * blockDim.x + threadIdx.x;
    if (i >= n8) return;
    __half* d = which ? g_Bh : g_Ah;
    const float4* s4 = (const float4*)s;
    float4 a = s4[2 * i], b = s4[2 * i + 1];
    union { uint4 u; __half h[8]; } o;
    o.h[0] = __float2half_rn(a.x); o.h[1] = __float2half_rn(a.y);
    o.h[2] = __float2half_rn(a.z); o.h[3] = __float2half_rn(a.w);
    o.h[4] = __float2half_rn(b.x); o.h[5] = __float2half_rn(b.y);
    o.h[6] = __float2half_rn(b.z); o.h[7] = __float2half_rn(b.w);
    ((uint4*)d)[i] = o.u;
}

// ---------------- kernel 1: fp16 mma.sync GEMM + relu + colsum ----------------
// colsum[n] = sum_m relu( (z2f @ W_proj^T)[m,n] + b_proj[n] )
#define BM 128
#define BN 128
#define BK 64                        /* k elems per chunk */
#define NST 3                        /* pipeline stages */
#define SST 36                       /* words per smem row: 32 data + 4 pad */
#define MAT_W (BM * SST)             /* 4608 words per matrix tile */
#define STAGE_W (2 * MAT_W)          /* A + B per stage */
#define NK (PIN / BK)                /* 147 chunks */
#define GEMM_SMEM (NST * STAGE_W * 4)  /* 110592 bytes */

__global__ __launch_bounds__(512, 1) void gemm_fd(const float* __restrict__ bias) {
    extern __shared__ uint32_t sh[];
    __shared__ float colsum_sh[BN];
    __shared__ float bias_sh[BN];

    const int tid  = threadIdx.x;
    const int lane = tid & 31;
    const int wid  = tid >> 5;        // 0..15
    const int g    = lane >> 2;       // 0..7
    const int t    = lane & 3;        // 0..3
    const int warp_m = wid & 3;       // 4 x 32 rows
    const int warp_n = wid >> 2;      // 4 x 32 cols
    const int m0 = blockIdx.x * BM;
    const int n0 = blockIdx.y * BN;

    if (tid < BN) { colsum_sh[tid] = 0.f; bias_sh[tid] = bias[n0 + tid]; }

    float acc[2][4][4];
#pragma unroll
    for (int a = 0; a < 2; ++a)
#pragma unroll
        for (int b = 0; b < 4; ++b)
#pragma unroll
            for (int c = 0; c < 4; ++c) acc[a][b][c] = 0.f;

    // --- loader setup: 2048 x 16B chunks per stage, 4 per thread ---
    const uint32_t sbase = smem_u32(sh);
    const __half* gp[4];
    uint32_t soff[4];                 // byte offset within a stage
#pragma unroll
    for (int i = 0; i < 4; ++i) {
        const int c = tid + i * 512;
        const int isA = (c < 1024);
        const int r = (c & 1023) >> 3;   // 0..127
        const int q = c & 7;             // 16B chunk within 128B row
        gp[i] = (isA ? (g_Ah + (size_t)(m0 + r) * PIN)
                     : (g_Bh + (size_t)(n0 + r) * PIN)) + q * 8;
        soff[i] = (uint32_t)(((isA ? 0 : MAT_W) + r * SST + q * 4) * 4);
    }

    auto load_stage = [&](int s, int kt) {
        const int kc = kt * BK;
        const uint32_t sb = sbase + (uint32_t)(s * STAGE_W * 4);
#pragma unroll
        for (int i = 0; i < 4; ++i)
            CP_ASYNC16(sb + soff[i], gp[i] + kc);
    };

    // prologue: stages 0,1
    load_stage(0, 0); CP_COMMIT();
    load_stage(1, 1); CP_COMMIT();

#pragma unroll 1
    for (int kt = 0; kt < NK; ++kt) {
        CP_WAIT1();                  // chunk kt resident
        __syncthreads();             // all warps done with chunk kt-1 (its stage is reload target)

        if (kt + 2 < NK) load_stage((kt + 2) % NST, kt + 2);
        CP_COMMIT();

        const uint32_t* Ab = sh + (kt % NST) * STAGE_W;
        const uint32_t* Bb = Ab + MAT_W;

#pragma unroll
        for (int ks2 = 0; ks2 < 32; ks2 += 8) {      // four k=16 slices of BK=64
            unsigned af[2][4];
#pragma unroll
            for (int mt = 0; mt < 2; ++mt) {
                const int rb = (warp_m * 32 + mt * 16 + g) * SST + ks2 + t;
                af[mt][0] = Ab[rb];
                af[mt][1] = Ab[rb + 8 * SST];
                af[mt][2] = Ab[rb + 4];
                af[mt][3] = Ab[rb + 8 * SST + 4];
            }
#pragma unroll
            for (int nt = 0; nt < 4; ++nt) {
                const int nb = (warp_n * 32 + nt * 8 + g) * SST + ks2 + t;
                const unsigned b0 = Bb[nb];
                const unsigned b1 = Bb[nb + 4];
#pragma unroll
                for (int mt = 0; mt < 2; ++mt) {
                    asm volatile(
                        "mma.sync.aligned.m16n8k16.row.col.f32.f16.f16.f32 "
                        "{%0,%1,%2,%3}, {%4,%5,%6,%7}, {%8,%9}, {%0,%1,%2,%3};"
                        : "+f"(acc[mt][nt][0]), "+f"(acc[mt][nt][1]),
                          "+f"(acc[mt][nt][2]), "+f"(acc[mt][nt][3])
                        : "r"(af[mt][0]), "r"(af[mt][1]), "r"(af[mt][2]), "r"(af[mt][3]),
                          "r"(b0), "r"(b1));
                }
            }
        }
    }
    __syncthreads();

    // ---- epilogue: relu(acc + bias), reduce all M rows -> per-column sums ----
#pragma unroll
    for (int nt = 0; nt < 4; ++nt) {
#pragma unroll
        for (int pc = 0; pc < 2; ++pc) {
            const int col = warp_n * 32 + nt * 8 + 2 * t + pc;
            const float bv = bias_sh[col];
            float v = fmaxf(acc[0][nt][pc]     + bv, 0.f)
                    + fmaxf(acc[0][nt][2 + pc] + bv, 0.f)
                    + fmaxf(acc[1][nt][pc]     + bv, 0.f)
                    + fmaxf(acc[1][nt][2 + pc] + bv, 0.f);
            v += __shfl_xor_sync(0xffffffffu, v, 4);
            v += __shfl_xor_sync(0xffffffffu, v, 8);
            v += __shfl_xor_sync(0xffffffffu, v, 16);
            if (g == 0) atomicAdd(&colsum_sh[col], v);
        }
    }
    __syncthreads();
    if (tid < BN) atomicAdd(&g_colsum[n0 + tid], colsum_sh[tid]);
}

// ---------------- kernel 2: S2[c] = colsum . W_fc[c, HID:] + BSZ*b_fc[c] ----------------
__global__ void s2_kernel(const float* __restrict__ Wfc, const float* __restrict__ bfc) {
    const int c = blockIdx.x;
    const int tid = threadIdx.x;
    float pacc = 0.f;
    for (int k = tid; k < POUT; k += 256)
        pacc += g_colsum[k] * Wfc[(long)c * KFC + HID + k];
#pragma unroll
    for (int off = 16; off > 0; off >>= 1)
        pacc += __shfl_down_sync(0xffffffffu, pacc, off);
    __shared__ float red[8];
    if ((tid & 31) == 0) red[tid >> 5] = pacc;
    __syncthreads();
    if (tid == 0) {
        float s = 0.f;
#pragma unroll
        for (int i = 0; i < 8; ++i) s += red[i];
        g_s2[c] = s + (float)BSZ * bfc[c];
    }
}

// ---------------- kernel 3: s1 = z1 @ W_fc[:, :HID]^T  (fp32) ----------------
#define S1_BM 128
#define S1_KS 8
#define S1_CHUNK (HID / S1_KS)
#define S1_KC 32

__global__ __launch_bounds__(256) void s1_kernel(const float* __restrict__ z1,
                                                 const float* __restrict__ Wfc) {
    __shared__ float zt[S1_KC][S1_BM + 4];
    __shared__ float ws[S1_KC][80];

    const int tid = threadIdx.x;
    const int tx = tid & 15;
    const int ty = tid >> 4;
    const int rb = blockIdx.x * S1_BM;
    const int kbase = blockIdx.y * S1_CHUNK;

    float acc[8][5];
#pragma unroll
    for (int i = 0; i < 8; ++i)
#pragma unroll
        for (int j = 0; j < 5; ++j) acc[i][j] = 0.f;

    for (int kc = kbase; kc < kbase + S1_CHUNK; kc += S1_KC) {
#pragma unroll
        for (int i = 0; i < 16; ++i) {
            const int idx = tid + i * 256;
            const int k = idx & 31, rr = idx >> 5;
            zt[k][rr] = z1[(long)(rb + rr) * HID + kc + k];
        }
#pragma unroll
        for (int i = 0; i < 10; ++i) {
            const int idx = tid + i * 256;
            const int c = idx % 80, k = idx / 80;
            ws[k][c] = (c < NC) ? Wfc[(long)c * KFC + kc + k] : 0.f;
        }
        __syncthreads();

#pragma unroll
        for (int k = 0; k < S1_KC; ++k) {
            const float4 za = *(const float4*)&zt[k][ty * 8];
            const float4 zb = *(const float4*)&zt[k][ty * 8 + 4];
            float w[5];
#pragma unroll
            for (int j = 0; j < 5; ++j) w[j] = ws[k][tx * 5 + j];
            const float zr[8] = {za.x, za.y, za.z, za.w, zb.x, zb.y, zb.z, zb.w};
#pragma unroll
            for (int i = 0; i < 8; ++i)
#pragma unroll
                for (int j = 0; j < 5; ++j) acc[i][j] += zr[i] * w[j];
        }
        __syncthreads();
    }

#pragma unroll
    for (int i = 0; i < 8; ++i) {
        const int row = rb + ty * 8 + i;
#pragma unroll
        for (int j = 0; j < 5; ++j) {
            const int c = tx * 5 + j;
            if (c < NC) atomicAdd(&g_s1[(long)row * NC + c], acc[i][j]);
        }
    }
}

// ---------------- kernel 4: out[i,c] = 2048*s1[i,c] + g_s2[c] ----------------
__global__ void final_kernel(float* __restrict__ out) {
    const int i = blockIdx.x * blockDim.x + threadIdx.x;
    if (i < BSZ * NC) out[i] = 2048.f * g_s1[i] + g_s2[i % NC];
}

// ---------------- launch ----------------
extern "C" void kernel_launch(void* const* d_in, const int* in_sizes, int n_in,
                              void* d_out, int out_size) {
    (void)in_sizes; (void)n_in; (void)out_size;
    const float* z1  = (const float*)d_in[0];
    const float* z2  = (const float*)d_in[1];
    const float* Wp  = (const float*)d_in[2];
    const float* bp  = (const float*)d_in[3];
    const float* Wfc = (const float*)d_in[4];
    const float* bfc = (const float*)d_in[5];
    float* out = (float*)d_out;

    cudaFuncSetAttribute(gemm_fd, cudaFuncAttributeMaxDynamicSharedMemorySize, GEMM_SMEM);

    zero_kernel<<<(BSZ * NC + 255) / 256, 256>>>();
    cvt8_kernel<<<(BSZ * PIN / 8 + 255) / 256, 256>>>(z2, 0, BSZ * PIN / 8);
    cvt8_kernel<<<(POUT * PIN / 8 + 255) / 256, 256>>>(Wp, 1, POUT * PIN / 8);
    gemm_fd<<<dim3(BSZ / BM, POUT / BN), 512, GEMM_SMEM>>>(bp);
    s1_kernel<<<dim3(BSZ / S1_BM, S1_KS), 256>>>(z1, Wfc);
    s2_kernel<<<NC, 256>>>(Wfc, bfc);
    final_kernel<<<(BSZ * NC + 255) / 256, 256>>>(out);
}

// round 10
// speedup vs baseline: 2.3071x; 1.0283x over previous
#include <cuda_runtime.h>
#include <cuda_fp16.h>
#include <cstdint>

#define BSZ   2048
#define HID   2048
#define PIN   9408
#define POUT  1024
#define NC    65
#define KFC   3072   /* HID + POUT */

// ---------------- scratch (no allocations allowed) ----------------
__device__ float g_colsum[POUT];
__device__ float g_s2[NC];
__device__ float g_s1[BSZ * NC];
__device__ __align__(16) __half g_Ah[BSZ * PIN];   // z2 in fp16
__device__ __align__(16) __half g_Bh[POUT * PIN];  // W_proj in fp16

// ---------------- helpers ----------------
__device__ __forceinline__ uint32_t smem_u32(const void* p) {
    uint32_t a;
    asm("{ .reg .u64 t; cvta.to.shared.u64 t, %1; cvt.u32.u64 %0, t; }" : "=r"(a) : "l"(p));
    return a;
}
#define CP_ASYNC16(sa, ga) \
    asm volatile("cp.async.cg.shared.global [%0], [%1], 16;" :: "r"((uint32_t)(sa)), "l"(ga) : "memory")
#define CP_COMMIT() asm volatile("cp.async.commit_group;" ::: "memory")
#define CP_WAIT2()  asm volatile("cp.async.wait_group 2;" ::: "memory")
#define LDSM_X4(r0, r1, r2, r3, addr) \
    asm volatile("ldmatrix.sync.aligned.m8n8.x4.shared.b16 {%0,%1,%2,%3}, [%4];" \
        : "=r"(r0), "=r"(r1), "=r"(r2), "=r"(r3) : "r"(addr))

// ---------------- kernel 0: zero scratch ----------------
__global__ void zero_kernel() {
    int i = blockIdx.x * blockDim.x + threadIdx.x;
    if (i < POUT) g_colsum[i] = 0.f;
    if (i < BSZ * NC) g_s1[i] = 0.f;
}

// ---------------- fp32 -> fp16 conversion (8 elems / thread) ----------------
__global__ void cvt8_kernel(const float* __restrict__ s, int which, int n8) {
    int i = blockIdx.x * blockDim.x + threadIdx.x;
    if (i >= n8) return;
    __half* d = which ? g_Bh : g_Ah;
    const float4* s4 = (const float4*)s;
    float4 a = s4[2 * i], b = s4[2 * i + 1];
    union { uint4 u; __half h[8]; } o;
    o.h[0] = __float2half_rn(a.x); o.h[1] = __float2half_rn(a.y);
    o.h[2] = __float2half_rn(a.z); o.h[3] = __float2half_rn(a.w);
    o.h[4] = __float2half_rn(b.x); o.h[5] = __float2half_rn(b.y);
    o.h[6] = __float2half_rn(b.z); o.h[7] = __float2half_rn(b.w);
    ((uint4*)d)[i] = o.u;
}

// ---------------- kernel 1: fp16 mma.sync GEMM + relu + colsum ----------------
// colsum[n] = sum_m relu( (z2f @ W_proj^T)[m,n] + b_proj[n] )
#define BM 128
#define BN 128
#define BK 64                        /* k elems per chunk */
#define NST 4                        /* pipeline stages */
#define SST 36                       /* words per smem row: 32 data + 4 pad */
#define MAT_W (BM * SST)             /* 4608 words per matrix tile */
#define STAGE_W (2 * MAT_W)          /* A + B per stage */
#define NK (PIN / BK)                /* 147 chunks */
#define GEMM_SMEM (NST * STAGE_W * 4)  /* 147456 bytes */

__global__ __launch_bounds__(512, 1) void gemm_fd(const float* __restrict__ bias) {
    extern __shared__ uint32_t sh[];
    __shared__ float colsum_sh[BN];
    __shared__ float bias_sh[BN];

    const int tid  = threadIdx.x;
    const int lane = tid & 31;
    const int wid  = tid >> 5;        // 0..15
    const int g    = lane >> 2;       // 0..7
    const int t    = lane & 3;        // 0..3
    const int warp_m = wid & 3;       // 4 x 32 rows
    const int warp_n = wid >> 2;      // 4 x 32 cols
    const int m0 = blockIdx.x * BM;
    const int n0 = blockIdx.y * BN;

    if (tid < BN) { colsum_sh[tid] = 0.f; bias_sh[tid] = bias[n0 + tid]; }

    float acc[2][4][4];
#pragma unroll
    for (int a = 0; a < 2; ++a)
#pragma unroll
        for (int b = 0; b < 4; ++b)
#pragma unroll
            for (int c = 0; c < 4; ++c) acc[a][b][c] = 0.f;

    const uint32_t sbase = smem_u32(sh);

    // --- ldmatrix per-lane addresses (bytes, relative to stage base) ---
    // A x4 for mt: matrices (m0-7,k0),(m8-15,k0),(m0-7,k8),(m8-15,k8)
    //   lane l: row = warp_m*32 + mt*16 + (l&15); kword = (l>>4)*4
    uint32_t aoff[2];
#pragma unroll
    for (int mt = 0; mt < 2; ++mt)
        aoff[mt] = (uint32_t)(((warp_m * 32 + mt * 16 + (lane & 15)) * SST
                               + ((lane >> 4) << 2)) * 4);
    // B x4 for j (covers nt=2j, 2j+1): matrices (n0-7,k0),(n0-7,k8),(n8-15,k0),(n8-15,k8)
    //   lane l: n = warp_n*32 + j*16 + ((l>>4)<<3) + (l&7); kword = ((l>>3)&1)*4
    uint32_t boff[2];
#pragma unroll
    for (int j = 0; j < 2; ++j)
        boff[j] = (uint32_t)((MAT_W + (warp_n * 32 + j * 16 + ((lane >> 4) << 3) + (lane & 7)) * SST
                              + (((lane >> 3) & 1) << 2)) * 4);

    // --- loader setup: 2048 x 16B chunks per stage, 4 per thread ---
    const __half* gp[4];
    uint32_t soff[4];
#pragma unroll
    for (int i = 0; i < 4; ++i) {
        const int c = tid + i * 512;
        const int isA = (c < 1024);
        const int r = (c & 1023) >> 3;
        const int q = c & 7;
        gp[i] = (isA ? (g_Ah + (size_t)(m0 + r) * PIN)
                     : (g_Bh + (size_t)(n0 + r) * PIN)) + q * 8;
        soff[i] = (uint32_t)(((isA ? 0 : MAT_W) + r * SST + q * 4) * 4);
    }

    auto load_stage = [&](int s, int kt) {
        const int kc = kt * BK;
        const uint32_t sb = sbase + (uint32_t)(s * STAGE_W * 4);
#pragma unroll
        for (int i = 0; i < 4; ++i)
            CP_ASYNC16(sb + soff[i], gp[i] + kc);
    };

    // prologue: stages 0,1,2
    load_stage(0, 0); CP_COMMIT();
    load_stage(1, 1); CP_COMMIT();
    load_stage(2, 2); CP_COMMIT();

#pragma unroll 1
    for (int kt = 0; kt < NK; ++kt) {
        CP_WAIT2();                  // chunk kt resident (<=2 newer groups outstanding)
        __syncthreads();             // all warps done with chunk kt-1 (its stage is reload target)

        if (kt + 3 < NK) load_stage((kt + 3) % NST, kt + 3);
        CP_COMMIT();

        const uint32_t stg = sbase + (uint32_t)((kt % NST) * STAGE_W * 4);

#pragma unroll
        for (int ks2 = 0; ks2 < 32; ks2 += 8) {      // four k=16 slices of BK=64
            const uint32_t kb = stg + (uint32_t)(ks2 * 4);
            unsigned af[2][4], bf[2][4];
            LDSM_X4(af[0][0], af[0][1], af[0][2], af[0][3], kb + aoff[0]);
            LDSM_X4(af[1][0], af[1][1], af[1][2], af[1][3], kb + aoff[1]);
            LDSM_X4(bf[0][0], bf[0][1], bf[0][2], bf[0][3], kb + boff[0]);
            LDSM_X4(bf[1][0], bf[1][1], bf[1][2], bf[1][3], kb + boff[1]);
#pragma unroll
            for (int nt = 0; nt < 4; ++nt) {
                const unsigned b0 = bf[nt >> 1][(nt & 1) * 2];
                const unsigned b1 = bf[nt >> 1][(nt & 1) * 2 + 1];
#pragma unroll
                for (int mt = 0; mt < 2; ++mt) {
                    asm volatile(
                        "mma.sync.aligned.m16n8k16.row.col.f32.f16.f16.f32 "
                        "{%0,%1,%2,%3}, {%4,%5,%6,%7}, {%8,%9}, {%0,%1,%2,%3};"
                        : "+f"(acc[mt][nt][0]), "+f"(acc[mt][nt][1]),
                          "+f"(acc[mt][nt][2]), "+f"(acc[mt][nt][3])
                        : "r"(af[mt][0]), "r"(af[mt][1]), "r"(af[mt][2]), "r"(af[mt][3]),
                          "r"(b0), "r"(b1));
                }
            }
        }
    }
    __syncthreads();

    // ---- epilogue: relu(acc + bias), reduce all M rows -> per-column sums ----
#pragma unroll
    for (int nt = 0; nt < 4; ++nt) {
#pragma unroll
        for (int pc = 0; pc < 2; ++pc) {
            const int col = warp_n * 32 + nt * 8 + 2 * t + pc;
            const float bv = bias_sh[col];
            float v = fmaxf(acc[0][nt][pc]     + bv, 0.f)
                    + fmaxf(acc[0][nt][2 + pc] + bv, 0.f)
                    + fmaxf(acc[1][nt][pc]     + bv, 0.f)
                    + fmaxf(acc[1][nt][2 + pc] + bv, 0.f);
            v += __shfl_xor_sync(0xffffffffu, v, 4);
            v += __shfl_xor_sync(0xffffffffu, v, 8);
            v += __shfl_xor_sync(0xffffffffu, v, 16);
            if (g == 0) atomicAdd(&colsum_sh[col], v);
        }
    }
    __syncthreads();
    if (tid < BN) atomicAdd(&g_colsum[n0 + tid], colsum_sh[tid]);
}

// ---------------- kernel 2: S2[c] = colsum . W_fc[c, HID:] + BSZ*b_fc[c] ----------------
__global__ void s2_kernel(const float* __restrict__ Wfc, const float* __restrict__ bfc) {
    const int c = blockIdx.x;
    const int tid = threadIdx.x;
    float pacc = 0.f;
    for (int k = tid; k < POUT; k += 256)
        pacc += g_colsum[k] * Wfc[(long)c * KFC + HID + k];
#pragma unroll
    for (int off = 16; off > 0; off >>= 1)
        pacc += __shfl_down_sync(0xffffffffu, pacc, off);
    __shared__ float red[8];
    if ((tid & 31) == 0) red[tid >> 5] = pacc;
    __syncthreads();
    if (tid == 0) {
        float s = 0.f;
#pragma unroll
        for (int i = 0; i < 8; ++i) s += red[i];
        g_s2[c] = s + (float)BSZ * bfc[c];
    }
}

// ---------------- kernel 3: s1 = z1 @ W_fc[:, :HID]^T  (fp32) ----------------
#define S1_BM 128
#define S1_KS 8
#define S1_CHUNK (HID / S1_KS)
#define S1_KC 32

__global__ __launch_bounds__(256) void s1_kernel(const float* __restrict__ z1,
                                                 const float* __restrict__ Wfc) {
    __shared__ float zt[S1_KC][S1_BM + 4];
    __shared__ float ws[S1_KC][80];

    const int tid = threadIdx.x;
    const int tx = tid & 15;
    const int ty = tid >> 4;
    const int rb = blockIdx.x * S1_BM;
    const int kbase = blockIdx.y * S1_CHUNK;

    float acc[8][5];
#pragma unroll
    for (int i = 0; i < 8; ++i)
#pragma unroll
        for (int j = 0; j < 5; ++j) acc[i][j] = 0.f;

    for (int kc = kbase; kc < kbase + S1_CHUNK; kc += S1_KC) {
#pragma unroll
        for (int i = 0; i < 16; ++i) {
            const int idx = tid + i * 256;
            const int k = idx & 31, rr = idx >> 5;
            zt[k][rr] = z1[(long)(rb + rr) * HID + kc + k];
        }
#pragma unroll
        for (int i = 0; i < 10; ++i) {
            const int idx = tid + i * 256;
            const int c = idx % 80, k = idx / 80;
            ws[k][c] = (c < NC) ? Wfc[(long)c * KFC + kc + k] : 0.f;
        }
        __syncthreads();

#pragma unroll
        for (int k = 0; k < S1_KC; ++k) {
            const float4 za = *(const float4*)&zt[k][ty * 8];
            const float4 zb = *(const float4*)&zt[k][ty * 8 + 4];
            float w[5];
#pragma unroll
            for (int j = 0; j < 5; ++j) w[j] = ws[k][tx * 5 + j];
            const float zr[8] = {za.x, za.y, za.z, za.w, zb.x, zb.y, zb.z, zb.w};
#pragma unroll
            for (int i = 0; i < 8; ++i)
#pragma unroll
                for (int j = 0; j < 5; ++j) acc[i][j] += zr[i] * w[j];
        }
        __syncthreads();
    }

#pragma unroll
    for (int i = 0; i < 8; ++i) {
        const int row = rb + ty * 8 + i;
#pragma unroll
        for (int j = 0; j < 5; ++j) {
            const int c = tx * 5 + j;
            if (c < NC) atomicAdd(&g_s1[(long)row * NC + c], acc[i][j]);
        }
    }
}

// ---------------- kernel 4: out[i,c] = 2048*s1[i,c] + g_s2[c] ----------------
__global__ void final_kernel(float* __restrict__ out) {
    const int i = blockIdx.x * blockDim.x + threadIdx.x;
    if (i < BSZ * NC) out[i] = 2048.f * g_s1[i] + g_s2[i % NC];
}

// ---------------- launch ----------------
extern "C" void kernel_launch(void* const* d_in, const int* in_sizes, int n_in,
                              void* d_out, int out_size) {
    (void)in_sizes; (void)n_in; (void)out_size;
    const float* z1  = (const float*)d_in[0];
    const float* z2  = (const float*)d_in[1];
    const float* Wp  = (const float*)d_in[2];
    const float* bp  = (const float*)d_in[3];
    const float* Wfc = (const float*)d_in[4];
    const float* bfc = (const float*)d_in[5];
    float* out = (float*)d_out;

    cudaFuncSetAttribute(gemm_fd, cudaFuncAttributeMaxDynamicSharedMemorySize, GEMM_SMEM);

    zero_kernel<<<(BSZ * NC + 255) / 256, 256>>>();
    cvt8_kernel<<<(BSZ * PIN / 8 + 255) / 256, 256>>>(z2, 0, BSZ * PIN / 8);
    cvt8_kernel<<<(POUT * PIN / 8 + 255) / 256, 256>>>(Wp, 1, POUT * PIN / 8);
    gemm_fd<<<dim3(BSZ / BM, POUT / BN), 512, GEMM_SMEM>>>(bp);
    s1_kernel<<<dim3(BSZ / S1_BM, S1_KS), 256>>>(z1, Wfc);
    s2_kernel<<<NC, 256>>>(Wfc, bfc);
    final_kernel<<<(BSZ * NC + 255) / 256, 256>>>(out);
}

// round 11
// speedup vs baseline: 2.4146x; 1.0466x over previous
#include <cuda_runtime.h>
#include <cuda_fp16.h>
#include <cstdint>

#define BSZ   2048
#define HID   2048
#define PIN   9408
#define POUT  1024
#define NC    65
#define KFC   3072   /* HID + POUT */

// ---------------- scratch (no allocations allowed) ----------------
__device__ float g_colsum[POUT];
__device__ float g_s2[NC];
__device__ float g_s1[BSZ * NC];
__device__ __align__(16) __half g_Ah[BSZ * PIN];   // z2 in fp16
__device__ __align__(16) __half g_Bh[POUT * PIN];  // W_proj in fp16

// ---------------- side stream for overlap (created pre-main, no device mem alloc in launch) ----
static cudaStream_t g_side = nullptr;
static cudaEvent_t  g_evFork = nullptr, g_evJoin = nullptr;
namespace {
struct SideInit {
    SideInit() {
        cudaStreamCreateWithFlags(&g_side, cudaStreamNonBlocking);
        cudaEventCreateWithFlags(&g_evFork, cudaEventDisableTiming);
        cudaEventCreateWithFlags(&g_evJoin, cudaEventDisableTiming);
    }
} g_sideInit;
}

// ---------------- helpers ----------------
__device__ __forceinline__ uint32_t smem_u32(const void* p) {
    uint32_t a;
    asm("{ .reg .u64 t; cvta.to.shared.u64 t, %1; cvt.u32.u64 %0, t; }" : "=r"(a) : "l"(p));
    return a;
}
#define CP_ASYNC16(sa, ga) \
    asm volatile("cp.async.cg.shared.global [%0], [%1], 16;" :: "r"((uint32_t)(sa)), "l"(ga) : "memory")
#define CP_COMMIT() asm volatile("cp.async.commit_group;" ::: "memory")
#define CP_WAIT1()  asm volatile("cp.async.wait_group 1;" ::: "memory")
#define LDSM_X4(r0, r1, r2, r3, addr) \
    asm volatile("ldmatrix.sync.aligned.m8n8.x4.shared.b16 {%0,%1,%2,%3}, [%4];" \
        : "=r"(r0), "=r"(r1), "=r"(r2), "=r"(r3) : "r"(addr))

// ---------------- kernel 0: zero scratch ----------------
__global__ void zero_kernel() {
    int i = blockIdx.x * blockDim.x + threadIdx.x;
    if (i < POUT) g_colsum[i] = 0.f;
    if (i < BSZ * NC) g_s1[i] = 0.f;
}

// ---------------- fp32 -> fp16 conversion (8 elems / thread) ----------------
__global__ void cvt8_kernel(const float* __restrict__ s, int which, int n8) {
    int i = blockIdx.x * blockDim.x + threadIdx.x;
    if (i >= n8) return;
    __half* d = which ? g_Bh : g_Ah;
    const float4* s4 = (const float4*)s;
    float4 a = s4[2 * i], b = s4[2 * i + 1];
    union { uint4 u; __half h[8]; } o;
    o.h[0] = __float2half_rn(a.x); o.h[1] = __float2half_rn(a.y);
    o.h[2] = __float2half_rn(a.z); o.h[3] = __float2half_rn(a.w);
    o.h[4] = __float2half_rn(b.x); o.h[5] = __float2half_rn(b.y);
    o.h[6] = __float2half_rn(b.z); o.h[7] = __float2half_rn(b.w);
    ((uint4*)d)[i] = o.u;
}

// ---------------- kernel 1: fp16 mma.sync GEMM + relu + colsum ----------------
// colsum[n] = sum_m relu( (z2f @ W_proj^T)[m,n] + b_proj[n] )
// 128x64 tiles, 256 threads (8 warps, 4x2 grid of 32x32 warp tiles), 2 CTAs/SM.
#define BM 128
#define BN 64
#define BK 64                        /* k elems per chunk */
#define NST 3                        /* pipeline stages */
#define SST 36                       /* words per smem row: 32 data + 4 pad */
#define MATA_W (BM * SST)            /* 4608 words: A tile */
#define MATB_W (BN * SST)            /* 2304 words: B tile */
#define STAGE_W (MATA_W + MATB_W)    /* 6912 words = 27648 B */
#define NK (PIN / BK)                /* 147 chunks */
#define GEMM_SMEM (NST * STAGE_W * 4)  /* 82944 bytes */
#define NCHUNK (BM * 8 + BN * 8)     /* 1536 16B-chunks per stage */

__global__ __launch_bounds__(256, 2) void gemm_fd(const float* __restrict__ bias) {
    extern __shared__ uint32_t sh[];
    __shared__ float colsum_sh[BN];
    __shared__ float bias_sh[BN];

    const int tid  = threadIdx.x;
    const int lane = tid & 31;
    const int wid  = tid >> 5;        // 0..7
    const int g    = lane >> 2;       // 0..7
    const int t    = lane & 3;        // 0..3
    const int warp_m = wid & 3;       // 4 x 32 rows
    const int warp_n = wid >> 2;      // 2 x 32 cols
    const int m0 = blockIdx.x * BM;
    const int n0 = blockIdx.y * BN;

    if (tid < BN) { colsum_sh[tid] = 0.f; bias_sh[tid] = bias[n0 + tid]; }

    float acc[2][4][4];
#pragma unroll
    for (int a = 0; a < 2; ++a)
#pragma unroll
        for (int b = 0; b < 4; ++b)
#pragma unroll
            for (int c = 0; c < 4; ++c) acc[a][b][c] = 0.f;

    const uint32_t sbase = smem_u32(sh);

    // --- ldmatrix per-lane addresses (bytes, relative to stage base) ---
    uint32_t aoff[2];
#pragma unroll
    for (int mt = 0; mt < 2; ++mt)
        aoff[mt] = (uint32_t)(((warp_m * 32 + mt * 16 + (lane & 15)) * SST
                               + ((lane >> 4) << 2)) * 4);
    uint32_t boff[2];
#pragma unroll
    for (int j = 0; j < 2; ++j)
        boff[j] = (uint32_t)((MATA_W + (warp_n * 32 + j * 16 + ((lane >> 4) << 3) + (lane & 7)) * SST
                              + (((lane >> 3) & 1) << 2)) * 4);

    // --- loader setup: 1536 x 16B chunks per stage, 6 per thread ---
    const __half* gp[6];
    uint32_t soff[6];
#pragma unroll
    for (int i = 0; i < 6; ++i) {
        const int c = tid + i * 256;
        const int isA = (c < BM * 8);
        const int r = (c & (BM * 8 - 1)) >> 3;   // A: 0..127 ; B: 0..63
        const int q = c & 7;
        gp[i] = (isA ? (g_Ah + (size_t)(m0 + r) * PIN)
                     : (g_Bh + (size_t)(n0 + r) * PIN)) + q * 8;
        soff[i] = (uint32_t)(((isA ? 0 : MATA_W) + r * SST + q * 4) * 4);
    }

    auto load_stage = [&](int s, int kt) {
        const int kc = kt * BK;
        const uint32_t sb = sbase + (uint32_t)(s * STAGE_W * 4);
#pragma unroll
        for (int i = 0; i < 6; ++i)
            CP_ASYNC16(sb + soff[i], gp[i] + kc);
    };

    // prologue: stages 0,1
    load_stage(0, 0); CP_COMMIT();
    load_stage(1, 1); CP_COMMIT();

#pragma unroll 1
    for (int kt = 0; kt < NK; ++kt) {
        CP_WAIT1();                  // chunk kt resident (<=1 newer group outstanding)
        __syncthreads();             // all warps done with chunk kt-1 (its stage is reload target)

        if (kt + 2 < NK) load_stage((kt + 2) % NST, kt + 2);
        CP_COMMIT();

        const uint32_t stg = sbase + (uint32_t)((kt % NST) * STAGE_W * 4);

#pragma unroll
        for (int ks2 = 0; ks2 < 32; ks2 += 8) {      // four k=16 slices of BK=64
            const uint32_t kb = stg + (uint32_t)(ks2 * 4);
            unsigned af[2][4], bf[2][4];
            LDSM_X4(af[0][0], af[0][1], af[0][2], af[0][3], kb + aoff[0]);
            LDSM_X4(af[1][0], af[1][1], af[1][2], af[1][3], kb + aoff[1]);
            LDSM_X4(bf[0][0], bf[0][1], bf[0][2], bf[0][3], kb + boff[0]);
            LDSM_X4(bf[1][0], bf[1][1], bf[1][2], bf[1][3], kb + boff[1]);
#pragma unroll
            for (int nt = 0; nt < 4; ++nt) {
                const unsigned b0 = bf[nt >> 1][(nt & 1) * 2];
                const unsigned b1 = bf[nt >> 1][(nt & 1) * 2 + 1];
#pragma unroll
                for (int mt = 0; mt < 2; ++mt) {
                    asm volatile(
                        "mma.sync.aligned.m16n8k16.row.col.f32.f16.f16.f32 "
                        "{%0,%1,%2,%3}, {%4,%5,%6,%7}, {%8,%9}, {%0,%1,%2,%3};"
                        : "+f"(acc[mt][nt][0]), "+f"(acc[mt][nt][1]),
                          "+f"(acc[mt][nt][2]), "+f"(acc[mt][nt][3])
                        : "r"(af[mt][0]), "r"(af[mt][1]), "r"(af[mt][2]), "r"(af[mt][3]),
                          "r"(b0), "r"(b1));
                }
            }
        }
    }
    __syncthreads();

    // ---- epilogue: relu(acc + bias), reduce all M rows -> per-column sums ----
#pragma unroll
    for (int nt = 0; nt < 4; ++nt) {
#pragma unroll
        for (int pc = 0; pc < 2; ++pc) {
            const int col = warp_n * 32 + nt * 8 + 2 * t + pc;
            const float bv = bias_sh[col];
            float v = fmaxf(acc[0][nt][pc]     + bv, 0.f)
                    + fmaxf(acc[0][nt][2 + pc] + bv, 0.f)
                    + fmaxf(acc[1][nt][pc]     + bv, 0.f)
                    + fmaxf(acc[1][nt][2 + pc] + bv, 0.f);
            v += __shfl_xor_sync(0xffffffffu, v, 4);
            v += __shfl_xor_sync(0xffffffffu, v, 8);
            v += __shfl_xor_sync(0xffffffffu, v, 16);
            if (g == 0) atomicAdd(&colsum_sh[col], v);
        }
    }
    __syncthreads();
    if (tid < BN) atomicAdd(&g_colsum[n0 + tid], colsum_sh[tid]);
}

// ---------------- kernel 2: S2[c] = colsum . W_fc[c, HID:] + BSZ*b_fc[c] ----------------
__global__ void s2_kernel(const float* __restrict__ Wfc, const float* __restrict__ bfc) {
    const int c = blockIdx.x;
    const int tid = threadIdx.x;
    float pacc = 0.f;
    for (int k = tid; k < POUT; k += 256)
        pacc += g_colsum[k] * Wfc[(long)c * KFC + HID + k];
#pragma unroll
    for (int off = 16; off > 0; off >>= 1)
        pacc += __shfl_down_sync(0xffffffffu, pacc, off);
    __shared__ float red[8];
    if ((tid & 31) == 0) red[tid >> 5] = pacc;
    __syncthreads();
    if (tid == 0) {
        float s = 0.f;
#pragma unroll
        for (int i = 0; i < 8; ++i) s += red[i];
        g_s2[c] = s + (float)BSZ * bfc[c];
    }
}

// ---------------- kernel 3: s1 = z1 @ W_fc[:, :HID]^T  (fp32) ----------------
#define S1_BM 128
#define S1_KS 8
#define S1_CHUNK (HID / S1_KS)
#define S1_KC 32

__global__ __launch_bounds__(256) void s1_kernel(const float* __restrict__ z1,
                                                 const float* __restrict__ Wfc) {
    __shared__ float zt[S1_KC][S1_BM + 4];
    __shared__ float ws[S1_KC][80];

    const int tid = threadIdx.x;
    const int tx = tid & 15;
    const int ty = tid >> 4;
    const int rb = blockIdx.x * S1_BM;
    const int kbase = blockIdx.y * S1_CHUNK;

    float acc[8][5];
#pragma unroll
    for (int i = 0; i < 8; ++i)
#pragma unroll
        for (int j = 0; j < 5; ++j) acc[i][j] = 0.f;

    for (int kc = kbase; kc < kbase + S1_CHUNK; kc += S1_KC) {
#pragma unroll
        for (int i = 0; i < 16; ++i) {
            const int idx = tid + i * 256;
            const int k = idx & 31, rr = idx >> 5;
            zt[k][rr] = z1[(long)(rb + rr) * HID + kc + k];
        }
#pragma unroll
        for (int i = 0; i < 10; ++i) {
            const int idx = tid + i * 256;
            const int c = idx % 80, k = idx / 80;
            ws[k][c] = (c < NC) ? Wfc[(long)c * KFC + kc + k] : 0.f;
        }
        __syncthreads();

#pragma unroll
        for (int k = 0; k < S1_KC; ++k) {
            const float4 za = *(const float4*)&zt[k][ty * 8];
            const float4 zb = *(const float4*)&zt[k][ty * 8 + 4];
            float w[5];
#pragma unroll
            for (int j = 0; j < 5; ++j) w[j] = ws[k][tx * 5 + j];
            const float zr[8] = {za.x, za.y, za.z, za.w, zb.x, zb.y, zb.z, zb.w};
#pragma unroll
            for (int i = 0; i < 8; ++i)
#pragma unroll
                for (int j = 0; j < 5; ++j) acc[i][j] += zr[i] * w[j];
        }
        __syncthreads();
    }

#pragma unroll
    for (int i = 0; i < 8; ++i) {
        const int row = rb + ty * 8 + i;
#pragma unroll
        for (int j = 0; j < 5; ++j) {
            const int c = tx * 5 + j;
            if (c < NC) atomicAdd(&g_s1[(long)row * NC + c], acc[i][j]);
        }
    }
}

// ---------------- kernel 4: out[i,c] = 2048*s1[i,c] + g_s2[c] ----------------
__global__ void final_kernel(float* __restrict__ out) {
    const int i = blockIdx.x * blockDim.x + threadIdx.x;
    if (i < BSZ * NC) out[i] = 2048.f * g_s1[i] + g_s2[i % NC];
}

// ---------------- launch ----------------
extern "C" void kernel_launch(void* const* d_in, const int* in_sizes, int n_in,
                              void* d_out, int out_size) {
    (void)in_sizes; (void)n_in; (void)out_size;
    const float* z1  = (const float*)d_in[0];
    const float* z2  = (const float*)d_in[1];
    const float* Wp  = (const float*)d_in[2];
    const float* bp  = (const float*)d_in[3];
    const float* Wfc = (const float*)d_in[4];
    const float* bfc = (const float*)d_in[5];
    float* out = (float*)d_out;

    cudaFuncSetAttribute(gemm_fd, cudaFuncAttributeMaxDynamicSharedMemorySize, GEMM_SMEM);

    zero_kernel<<<(BSZ * NC + 255) / 256, 256>>>();

    const bool overlap = (g_side != nullptr) && (g_evFork != nullptr) && (g_evJoin != nullptr);
    if (overlap) {
        // fork: run s1 on the side stream concurrently with cvt+gemm
        cudaEventRecord(g_evFork, 0);
        cudaStreamWaitEvent(g_side, g_evFork, 0);
        s1_kernel<<<dim3(BSZ / S1_BM, S1_KS), 256, 0, g_side>>>(z1, Wfc);
        cudaEventRecord(g_evJoin, g_side);
    }

    cvt8_kernel<<<(BSZ * PIN / 8 + 255) / 256, 256>>>(z2, 0, BSZ * PIN / 8);
    cvt8_kernel<<<(POUT * PIN / 8 + 255) / 256, 256>>>(Wp, 1, POUT * PIN / 8);
    gemm_fd<<<dim3(BSZ / BM, POUT / BN), 256, GEMM_SMEM>>>(bp);

    if (!overlap)
        s1_kernel<<<dim3(BSZ / S1_BM, S1_KS), 256>>>(z1, Wfc);

    s2_kernel<<<NC, 256>>>(Wfc, bfc);

    if (overlap)
        cudaStreamWaitEvent(0, g_evJoin, 0);

    final_kernel<<<(BSZ * NC + 255) / 256, 256>>>(out);
}